// round 2
// baseline (speedup 1.0000x reference)
#include <cuda_runtime.h>
#include <cuda_bf16.h>
#include <cstdint>

// Problem constants
#define NN 50000
#define NE 150000
#define DF 512
#define NH 512
#define NC 47
#define NADJ (NE + NN)

// ---------------- scratch (static __device__ — no allocation) ----------------
__device__ int   g_deg[NN];
__device__ __align__(16) float g_dinv[NN];
__device__ int   g_incl[NN];
__device__ int   g_bsum[128];
__device__ int   g_offs[NN + 1];
__device__ int   g_cursor[NN];
__device__ int   g_adj[NADJ];
__device__ __align__(16) float g_h1[(size_t)NN * NH];   // dinv-scaled x@W1
__device__ __align__(16) float g_a1[(size_t)NN * NH];   // relu(agg1 + b1)
__device__ __align__(16) float g_h2[(size_t)NN * NC];   // dinv-scaled a1@W2

// ---------------- graph prep ----------------
__global__ void k_init_deg() {
    int i = blockIdx.x * blockDim.x + threadIdx.x;
    if (i < NN) g_deg[i] = 1;  // self loop
}

__global__ void k_count_deg(const int* __restrict__ ecol) {
    int e = blockIdx.x * blockDim.x + threadIdx.x;
    if (e < NE) atomicAdd(&g_deg[ecol[e]], 1);
}

__global__ void k_dinv() {
    int i = blockIdx.x * blockDim.x + threadIdx.x;
    if (i < NN) g_dinv[i] = rsqrtf((float)g_deg[i]);
}

__global__ void k_scan_block() {
    __shared__ int s[512];
    int i = blockIdx.x * 512 + threadIdx.x;
    int v = (i < NN) ? g_deg[i] : 0;
    s[threadIdx.x] = v;
    __syncthreads();
    for (int off = 1; off < 512; off <<= 1) {
        int t = (threadIdx.x >= off) ? s[threadIdx.x - off] : 0;
        __syncthreads();
        s[threadIdx.x] += t;
        __syncthreads();
    }
    if (i < NN) g_incl[i] = s[threadIdx.x];
    if (threadIdx.x == 511) g_bsum[blockIdx.x] = s[511];
}

__global__ void k_scan_bsum(int nblocks) {
    if (threadIdx.x == 0 && blockIdx.x == 0) {
        int acc = 0;
        for (int i = 0; i < nblocks; i++) {
            int v = g_bsum[i];
            g_bsum[i] = acc;   // exclusive
            acc += v;
        }
    }
}

__global__ void k_scan_finish() {
    int i = blockIdx.x * blockDim.x + threadIdx.x;
    if (i < NN) {
        int e = g_incl[i] - g_deg[i] + g_bsum[i / 512];
        g_offs[i] = e;
        g_cursor[i] = e;
    }
    if (i == 0) g_offs[NN] = NADJ;
}

__global__ void k_scatter(const int* __restrict__ erow,
                          const int* __restrict__ ecol) {
    int t = blockIdx.x * blockDim.x + threadIdx.x;
    if (t < NE) {
        int c = ecol[t];
        int p = atomicAdd(&g_cursor[c], 1);
        g_adj[p] = erow[t];
    } else if (t < NADJ) {
        int i = t - NE;
        int p = atomicAdd(&g_cursor[i], 1);
        g_adj[p] = i;
    }
}

// ---------------- GEMM1: g_h1[m,f] = dinv[m] * sum_k x[m,k] * W1[k,f] ----------------
// BM=128, BN=64, BK=16; 256 threads; 8x4 per-thread tile.
__global__ __launch_bounds__(256) void k_gemm1(const float* __restrict__ A,
                                               const float* __restrict__ B) {
    __shared__ __align__(16) float As[16][132];  // [k][row], padded
    __shared__ __align__(16) float Bs[16][64];   // [k][col]
    const int tid  = threadIdx.x;
    const int tcol = tid & 15;   // 0..15 -> 4 cols each
    const int trow = tid >> 4;   // 0..15 -> 8 rows each
    const int rowBase = blockIdx.y * 128;
    const int colBase = blockIdx.x * 64;

    float acc[8][4];
#pragma unroll
    for (int i = 0; i < 8; i++)
#pragma unroll
        for (int j = 0; j < 4; j++) acc[i][j] = 0.f;

    for (int k0 = 0; k0 < DF; k0 += 16) {
        // load A tile: 128 rows x 16 k = 512 float4, 2 per thread
#pragma unroll
        for (int i = 0; i < 2; i++) {
            int idx = tid + i * 256;
            int r = idx >> 2, q = idx & 3;
            int gr = rowBase + r;
            float4 v = make_float4(0.f, 0.f, 0.f, 0.f);
            if (gr < NN) v = *(const float4*)(A + (size_t)gr * DF + k0 + q * 4);
            As[q * 4 + 0][r] = v.x;
            As[q * 4 + 1][r] = v.y;
            As[q * 4 + 2][r] = v.z;
            As[q * 4 + 3][r] = v.w;
        }
        // load B tile: 16 rows x 64 cols = 256 float4, 1 per thread
        {
            int r = tid >> 4, q = tid & 15;
            float4 v = *(const float4*)(B + (size_t)(k0 + r) * NH + colBase + q * 4);
            *(float4*)(&Bs[r][q * 4]) = v;
        }
        __syncthreads();
#pragma unroll
        for (int k = 0; k < 16; k++) {
            float a[8], b[4];
            *(float4*)(a)     = *(const float4*)(&As[k][trow * 8]);
            *(float4*)(a + 4) = *(const float4*)(&As[k][trow * 8 + 4]);
            *(float4*)(b)     = *(const float4*)(&Bs[k][tcol * 4]);
#pragma unroll
            for (int i = 0; i < 8; i++)
#pragma unroll
                for (int j = 0; j < 4; j++) acc[i][j] += a[i] * b[j];
        }
        __syncthreads();
    }
#pragma unroll
    for (int i = 0; i < 8; i++) {
        int gr = rowBase + trow * 8 + i;
        if (gr < NN) {
            float d = g_dinv[gr];
            float4 o = make_float4(d * acc[i][0], d * acc[i][1],
                                   d * acc[i][2], d * acc[i][3]);
            *(float4*)(g_h1 + (size_t)gr * NH + colBase + tcol * 4) = o;
        }
    }
}

// ---------------- agg1: a1[i,f] = relu(dinv[i]*sum_{adj} h1[row,f] + b1[f]) ----------------
__global__ __launch_bounds__(128) void k_agg1(const float* __restrict__ b1) {
    const int node = blockIdx.x;
    const int f = threadIdx.x * 4;  // 128 threads x float4 = 512
    const int s = g_offs[node], e = g_offs[node + 1];
    float4 acc = make_float4(0.f, 0.f, 0.f, 0.f);
    for (int p = s; p < e; p++) {
        int r = g_adj[p];
        float4 v = *(const float4*)(g_h1 + (size_t)r * NH + f);
        acc.x += v.x; acc.y += v.y; acc.z += v.z; acc.w += v.w;
    }
    float d = g_dinv[node];
    float4 bb = *(const float4*)(b1 + f);
    float4 o;
    o.x = fmaxf(d * acc.x + bb.x, 0.f);
    o.y = fmaxf(d * acc.y + bb.y, 0.f);
    o.z = fmaxf(d * acc.z + bb.z, 0.f);
    o.w = fmaxf(d * acc.w + bb.w, 0.f);
    *(float4*)(g_a1 + (size_t)node * NH + f) = o;
}

// ---------------- GEMM2: g_h2[m,c] = dinv[m] * sum_k a1[m,k] * W2[k,c] ----------------
// BM=128, BN=64 (covers 47 with guard), BK=16; 256 threads; 8x4 tile.
__global__ __launch_bounds__(256) void k_gemm2(const float* __restrict__ B) {
    __shared__ __align__(16) float As[16][132];
    __shared__ __align__(16) float Bs[16][64];
    const int tid  = threadIdx.x;
    const int tcol = tid & 15;
    const int trow = tid >> 4;
    const int rowBase = blockIdx.y * 128;

    float acc[8][4];
#pragma unroll
    for (int i = 0; i < 8; i++)
#pragma unroll
        for (int j = 0; j < 4; j++) acc[i][j] = 0.f;

    for (int k0 = 0; k0 < NH; k0 += 16) {
#pragma unroll
        for (int i = 0; i < 2; i++) {
            int idx = tid + i * 256;
            int r = idx >> 2, q = idx & 3;
            int gr = rowBase + r;
            float4 v = make_float4(0.f, 0.f, 0.f, 0.f);
            if (gr < NN) v = *(const float4*)(g_a1 + (size_t)gr * NH + k0 + q * 4);
            As[q * 4 + 0][r] = v.x;
            As[q * 4 + 1][r] = v.y;
            As[q * 4 + 2][r] = v.z;
            As[q * 4 + 3][r] = v.w;
        }
        // B tile 16x64 scalar loads with col guard (W2 row stride = 47)
#pragma unroll
        for (int i = 0; i < 4; i++) {
            int idx = tid + i * 256;
            int r = idx >> 6, c = idx & 63;
            Bs[r][c] = (c < NC) ? B[(size_t)(k0 + r) * NC + c] : 0.f;
        }
        __syncthreads();
#pragma unroll
        for (int k = 0; k < 16; k++) {
            float a[8], b[4];
            *(float4*)(a)     = *(const float4*)(&As[k][trow * 8]);
            *(float4*)(a + 4) = *(const float4*)(&As[k][trow * 8 + 4]);
            *(float4*)(b)     = *(const float4*)(&Bs[k][tcol * 4]);
#pragma unroll
            for (int i = 0; i < 8; i++)
#pragma unroll
                for (int j = 0; j < 4; j++) acc[i][j] += a[i] * b[j];
        }
        __syncthreads();
    }
#pragma unroll
    for (int i = 0; i < 8; i++) {
        int gr = rowBase + trow * 8 + i;
        if (gr < NN) {
            float d = g_dinv[gr];
#pragma unroll
            for (int j = 0; j < 4; j++) {
                int c = tcol * 4 + j;
                if (c < NC) g_h2[(size_t)gr * NC + c] = d * acc[i][j];
            }
        }
    }
}

// ---------------- agg2: out[i,c] = dinv[i]*sum_{adj} h2[row,c] + b2[c] ----------------
__global__ __launch_bounds__(256) void k_agg2(const float* __restrict__ b2,
                                              float* __restrict__ out) {
    int node = blockIdx.x * 8 + (threadIdx.x >> 5);
    if (node >= NN) return;
    int lane = threadIdx.x & 31;
    int s = g_offs[node], e = g_offs[node + 1];
    float a0 = 0.f, a1 = 0.f;
    for (int p = s; p < e; p++) {
        int r = g_adj[p];
        const float* gp = g_h2 + (size_t)r * NC;
        a0 += gp[lane];
        if (lane + 32 < NC) a1 += gp[lane + 32];
    }
    float d = g_dinv[node];
    out[(size_t)node * NC + lane] = d * a0 + b2[lane];
    if (lane + 32 < NC)
        out[(size_t)node * NC + lane + 32] = d * a1 + b2[lane + 32];
}

// ---------------- launch ----------------
extern "C" void kernel_launch(void* const* d_in, const int* in_sizes, int n_in,
                              void* d_out, int out_size) {
    const float* x  = (const float*)d_in[0];
    const int*   ei = (const int*)d_in[1];   // [2, NE] int32 (JAX x64 disabled)
    const float* W1 = (const float*)d_in[2];
    const float* b1 = (const float*)d_in[3];
    const float* W2 = (const float*)d_in[4];
    const float* b2 = (const float*)d_in[5];
    float* out = (float*)d_out;

    const int* erow = ei;        // edge_index[0] = source
    const int* ecol = ei + NE;   // edge_index[1] = target

    // graph prep
    k_init_deg<<<(NN + 255) / 256, 256>>>();
    k_count_deg<<<(NE + 255) / 256, 256>>>(ecol);
    k_dinv<<<(NN + 255) / 256, 256>>>();
    int nsb = (NN + 511) / 512;  // 98
    k_scan_block<<<nsb, 512>>>();
    k_scan_bsum<<<1, 32>>>(nsb);
    k_scan_finish<<<(NN + 255) / 256, 256>>>();
    k_scatter<<<(NADJ + 255) / 256, 256>>>(erow, ecol);

    // layer 1
    dim3 g1(NH / 64, (NN + 127) / 128);
    k_gemm1<<<g1, 256>>>(x, W1);
    k_agg1<<<NN, 128>>>(b1);

    // layer 2
    dim3 g2(1, (NN + 127) / 128);
    k_gemm2<<<g2, 256>>>(W2);
    k_agg2<<<(NN + 7) / 8, 256>>>(b2, out);
}

// round 3
// speedup vs baseline: 1.7434x; 1.7434x over previous
#include <cuda_runtime.h>
#include <cuda_bf16.h>
#include <cstdint>

// Problem constants
#define NN 50000
#define NE 150000
#define DF 512
#define NH 512
#define NC 47
#define NADJ (NE + NN)

// ---------------- scratch (static __device__ — no allocation) ----------------
__device__ int   g_deg[NN];
__device__ __align__(16) float g_dinv[NN];
__device__ int   g_incl[NN];
__device__ int   g_bsum[128];
__device__ int   g_offs[NN + 1];
__device__ int   g_cursor[NN];
__device__ int   g_adj[NADJ];
__device__ __align__(16) float g_h1[(size_t)NN * NH];   // dinv-scaled x@W1
__device__ __align__(16) float g_a1[(size_t)NN * NH];   // relu(agg1 + b1)
__device__ __align__(16) float g_h2[(size_t)NN * NC];   // dinv-scaled a1@W2

// ---------------- graph prep ----------------
__global__ void k_init_deg() {
    int i = blockIdx.x * blockDim.x + threadIdx.x;
    if (i < NN) g_deg[i] = 1;  // self loop
}

__global__ void k_count_deg(const int* __restrict__ ecol) {
    int e = blockIdx.x * blockDim.x + threadIdx.x;
    if (e < NE) atomicAdd(&g_deg[ecol[e]], 1);
}

__global__ void k_dinv() {
    int i = blockIdx.x * blockDim.x + threadIdx.x;
    if (i < NN) g_dinv[i] = rsqrtf((float)g_deg[i]);
}

__global__ void k_scan_block() {
    __shared__ int s[512];
    int i = blockIdx.x * 512 + threadIdx.x;
    int v = (i < NN) ? g_deg[i] : 0;
    s[threadIdx.x] = v;
    __syncthreads();
    for (int off = 1; off < 512; off <<= 1) {
        int t = (threadIdx.x >= off) ? s[threadIdx.x - off] : 0;
        __syncthreads();
        s[threadIdx.x] += t;
        __syncthreads();
    }
    if (i < NN) g_incl[i] = s[threadIdx.x];
    if (threadIdx.x == 511) g_bsum[blockIdx.x] = s[511];
}

__global__ void k_scan_bsum(int nblocks) {
    if (threadIdx.x == 0 && blockIdx.x == 0) {
        int acc = 0;
        for (int i = 0; i < nblocks; i++) {
            int v = g_bsum[i];
            g_bsum[i] = acc;   // exclusive
            acc += v;
        }
    }
}

__global__ void k_scan_finish() {
    int i = blockIdx.x * blockDim.x + threadIdx.x;
    if (i < NN) {
        int e = g_incl[i] - g_deg[i] + g_bsum[i / 512];
        g_offs[i] = e;
        g_cursor[i] = e;
    }
    if (i == 0) g_offs[NN] = NADJ;
}

__global__ void k_scatter(const int* __restrict__ erow,
                          const int* __restrict__ ecol) {
    int t = blockIdx.x * blockDim.x + threadIdx.x;
    if (t < NE) {
        int c = ecol[t];
        int p = atomicAdd(&g_cursor[c], 1);
        g_adj[p] = erow[t];
    } else if (t < NADJ) {
        int i = t - NE;
        int p = atomicAdd(&g_cursor[i], 1);
        g_adj[p] = i;
    }
}

// ---------------- helpers ----------------
__device__ __forceinline__ uint32_t f2tf32(float f) {
    uint32_t u;
    asm("cvt.rna.tf32.f32 %0, %1;" : "=r"(u) : "f"(f));
    return u;
}

__device__ __forceinline__ void mma_tf32(float& c0, float& c1, float& c2, float& c3,
                                         uint32_t a0, uint32_t a1, uint32_t a2, uint32_t a3,
                                         uint32_t b0, uint32_t b1) {
    asm volatile(
        "mma.sync.aligned.m16n8k8.row.col.f32.tf32.tf32.f32 "
        "{%0,%1,%2,%3},{%4,%5,%6,%7},{%8,%9},{%0,%1,%2,%3};"
        : "+f"(c0), "+f"(c1), "+f"(c2), "+f"(c3)
        : "r"(a0), "r"(a1), "r"(a2), "r"(a3), "r"(b0), "r"(b1));
}

// ---------------- GEMM1 (TF32 tensor cores) ----------------
// g_h1[m,f] = dinv[m] * sum_k x[m,k] * W1[k,f]
// BM=128, BN=128, BK=32; 256 threads = 8 warps (4 M x 2 N); warp tile 32x64.
__global__ __launch_bounds__(256) void k_gemm1_tf32(const float* __restrict__ A,
                                                    const float* __restrict__ B) {
    __shared__ __align__(16) uint32_t As[128][36];   // [m][k], pad 36 (conflict-free frags)
    __shared__ __align__(16) uint32_t Bs[32][132];   // [k][n], pad 132

    const int tid = threadIdx.x;
    const int lane = tid & 31;
    const int warp = tid >> 5;
    const int wm = warp & 3;          // 0..3  (M)
    const int wn = warp >> 2;         // 0..1  (N)
    const int gp = lane >> 2;         // 0..7
    const int tq = lane & 3;          // 0..3

    const int rowBase = blockIdx.y * 128;
    const int colBase = blockIdx.x * 128;
    const int warpRow = wm * 32;
    const int warpCol = wn * 64;

    float acc[2][8][4];
#pragma unroll
    for (int mi = 0; mi < 2; mi++)
#pragma unroll
        for (int ni = 0; ni < 8; ni++)
#pragma unroll
            for (int j = 0; j < 4; j++) acc[mi][ni][j] = 0.f;

    for (int k0 = 0; k0 < DF; k0 += 32) {
        // ---- load A tile: 128 rows x 32 k = 1024 float4 -> 4 per thread
#pragma unroll
        for (int i = 0; i < 4; i++) {
            int fid = tid + i * 256;
            int r = fid >> 3;        // 0..127
            int q = fid & 7;         // float4 index within 32 k
            int gr = rowBase + r;
            float4 v = make_float4(0.f, 0.f, 0.f, 0.f);
            if (gr < NN) v = __ldg((const float4*)(A + (size_t)gr * DF + k0 + q * 4));
            uint4 u;
            u.x = f2tf32(v.x); u.y = f2tf32(v.y);
            u.z = f2tf32(v.z); u.w = f2tf32(v.w);
            *(uint4*)(&As[r][q * 4]) = u;
        }
        // ---- load B tile: 32 k-rows x 128 cols = 1024 float4 -> 4 per thread
#pragma unroll
        for (int i = 0; i < 4; i++) {
            int fid = tid + i * 256;
            int r = fid >> 5;        // 0..31
            int q = fid & 31;        // float4 index within 128 cols
            float4 v = __ldg((const float4*)(B + (size_t)(k0 + r) * NH + colBase + q * 4));
            uint4 u;
            u.x = f2tf32(v.x); u.y = f2tf32(v.y);
            u.z = f2tf32(v.z); u.w = f2tf32(v.w);
            *(uint4*)(&Bs[r][q * 4]) = u;
        }
        __syncthreads();

#pragma unroll
        for (int kk = 0; kk < 32; kk += 8) {
            uint32_t a[2][4];
#pragma unroll
            for (int mi = 0; mi < 2; mi++) {
                int r0 = warpRow + mi * 16 + gp;
                a[mi][0] = As[r0][kk + tq];
                a[mi][1] = As[r0 + 8][kk + tq];
                a[mi][2] = As[r0][kk + tq + 4];
                a[mi][3] = As[r0 + 8][kk + tq + 4];
            }
            uint32_t b[8][2];
#pragma unroll
            for (int ni = 0; ni < 8; ni++) {
                int c = warpCol + ni * 8 + gp;
                b[ni][0] = Bs[kk + tq][c];
                b[ni][1] = Bs[kk + tq + 4][c];
            }
#pragma unroll
            for (int mi = 0; mi < 2; mi++)
#pragma unroll
                for (int ni = 0; ni < 8; ni++)
                    mma_tf32(acc[mi][ni][0], acc[mi][ni][1],
                             acc[mi][ni][2], acc[mi][ni][3],
                             a[mi][0], a[mi][1], a[mi][2], a[mi][3],
                             b[ni][0], b[ni][1]);
        }
        __syncthreads();
    }

    // ---- epilogue: scale rows by dinv, store
#pragma unroll
    for (int mi = 0; mi < 2; mi++) {
        int r0 = rowBase + warpRow + mi * 16 + gp;
        int r1 = r0 + 8;
        float d0 = (r0 < NN) ? g_dinv[r0] : 0.f;
        float d1 = (r1 < NN) ? g_dinv[r1] : 0.f;
#pragma unroll
        for (int ni = 0; ni < 8; ni++) {
            int c = colBase + warpCol + ni * 8 + tq * 2;
            if (r0 < NN) {
                float2 o = make_float2(d0 * acc[mi][ni][0], d0 * acc[mi][ni][1]);
                *(float2*)(g_h1 + (size_t)r0 * NH + c) = o;
            }
            if (r1 < NN) {
                float2 o = make_float2(d1 * acc[mi][ni][2], d1 * acc[mi][ni][3]);
                *(float2*)(g_h1 + (size_t)r1 * NH + c) = o;
            }
        }
    }
}

// ---------------- agg1: a1[i,f] = relu(dinv[i]*sum_{adj} h1[row,f] + b1[f]) ----------------
__global__ __launch_bounds__(128) void k_agg1(const float* __restrict__ b1) {
    const int node = blockIdx.x;
    const int f = threadIdx.x * 4;  // 128 threads x float4 = 512
    const int s = g_offs[node], e = g_offs[node + 1];
    float4 acc = make_float4(0.f, 0.f, 0.f, 0.f);
    for (int p = s; p < e; p++) {
        int r = g_adj[p];
        float4 v = *(const float4*)(g_h1 + (size_t)r * NH + f);
        acc.x += v.x; acc.y += v.y; acc.z += v.z; acc.w += v.w;
    }
    float d = g_dinv[node];
    float4 bb = *(const float4*)(b1 + f);
    float4 o;
    o.x = fmaxf(d * acc.x + bb.x, 0.f);
    o.y = fmaxf(d * acc.y + bb.y, 0.f);
    o.z = fmaxf(d * acc.z + bb.z, 0.f);
    o.w = fmaxf(d * acc.w + bb.w, 0.f);
    *(float4*)(g_a1 + (size_t)node * NH + f) = o;
}

// ---------------- GEMM2: g_h2[m,c] = dinv[m] * sum_k a1[m,k] * W2[k,c] ----------------
// BM=128, BN=64 (covers 47 with guard), BK=16; 256 threads; 8x4 tile (fp32).
__global__ __launch_bounds__(256) void k_gemm2(const float* __restrict__ B) {
    __shared__ __align__(16) float As[16][132];
    __shared__ __align__(16) float Bs[16][64];
    const int tid  = threadIdx.x;
    const int tcol = tid & 15;
    const int trow = tid >> 4;
    const int rowBase = blockIdx.y * 128;

    float acc[8][4];
#pragma unroll
    for (int i = 0; i < 8; i++)
#pragma unroll
        for (int j = 0; j < 4; j++) acc[i][j] = 0.f;

    for (int k0 = 0; k0 < NH; k0 += 16) {
#pragma unroll
        for (int i = 0; i < 2; i++) {
            int idx = tid + i * 256;
            int r = idx >> 2, q = idx & 3;
            int gr = rowBase + r;
            float4 v = make_float4(0.f, 0.f, 0.f, 0.f);
            if (gr < NN) v = *(const float4*)(g_a1 + (size_t)gr * NH + k0 + q * 4);
            As[q * 4 + 0][r] = v.x;
            As[q * 4 + 1][r] = v.y;
            As[q * 4 + 2][r] = v.z;
            As[q * 4 + 3][r] = v.w;
        }
        // B tile 16x64 scalar loads with col guard (W2 row stride = 47)
#pragma unroll
        for (int i = 0; i < 4; i++) {
            int idx = tid + i * 256;
            int r = idx >> 6, c = idx & 63;
            Bs[r][c] = (c < NC) ? B[(size_t)(k0 + r) * NC + c] : 0.f;
        }
        __syncthreads();
#pragma unroll
        for (int k = 0; k < 16; k++) {
            float a[8], b[4];
            *(float4*)(a)     = *(const float4*)(&As[k][trow * 8]);
            *(float4*)(a + 4) = *(const float4*)(&As[k][trow * 8 + 4]);
            *(float4*)(b)     = *(const float4*)(&Bs[k][tcol * 4]);
#pragma unroll
            for (int i = 0; i < 8; i++)
#pragma unroll
                for (int j = 0; j < 4; j++) acc[i][j] += a[i] * b[j];
        }
        __syncthreads();
    }
#pragma unroll
    for (int i = 0; i < 8; i++) {
        int gr = rowBase + trow * 8 + i;
        if (gr < NN) {
            float d = g_dinv[gr];
#pragma unroll
            for (int j = 0; j < 4; j++) {
                int c = tcol * 4 + j;
                if (c < NC) g_h2[(size_t)gr * NC + c] = d * acc[i][j];
            }
        }
    }
}

// ---------------- agg2: out[i,c] = dinv[i]*sum_{adj} h2[row,c] + b2[c] ----------------
__global__ __launch_bounds__(256) void k_agg2(const float* __restrict__ b2,
                                              float* __restrict__ out) {
    int node = blockIdx.x * 8 + (threadIdx.x >> 5);
    if (node >= NN) return;
    int lane = threadIdx.x & 31;
    int s = g_offs[node], e = g_offs[node + 1];
    float a0 = 0.f, a1 = 0.f;
    for (int p = s; p < e; p++) {
        int r = g_adj[p];
        const float* gp = g_h2 + (size_t)r * NC;
        a0 += gp[lane];
        if (lane + 32 < NC) a1 += gp[lane + 32];
    }
    float d = g_dinv[node];
    out[(size_t)node * NC + lane] = d * a0 + b2[lane];
    if (lane + 32 < NC)
        out[(size_t)node * NC + lane + 32] = d * a1 + b2[lane + 32];
}

// ---------------- launch ----------------
extern "C" void kernel_launch(void* const* d_in, const int* in_sizes, int n_in,
                              void* d_out, int out_size) {
    const float* x  = (const float*)d_in[0];
    const int*   ei = (const int*)d_in[1];   // [2, NE] int32 (JAX x64 disabled)
    const float* W1 = (const float*)d_in[2];
    const float* b1 = (const float*)d_in[3];
    const float* W2 = (const float*)d_in[4];
    const float* b2 = (const float*)d_in[5];
    float* out = (float*)d_out;

    const int* erow = ei;        // edge_index[0] = source
    const int* ecol = ei + NE;   // edge_index[1] = target

    // graph prep
    k_init_deg<<<(NN + 255) / 256, 256>>>();
    k_count_deg<<<(NE + 255) / 256, 256>>>(ecol);
    k_dinv<<<(NN + 255) / 256, 256>>>();
    int nsb = (NN + 511) / 512;  // 98
    k_scan_block<<<nsb, 512>>>();
    k_scan_bsum<<<1, 32>>>(nsb);
    k_scan_finish<<<(NN + 255) / 256, 256>>>();
    k_scatter<<<(NADJ + 255) / 256, 256>>>(erow, ecol);

    // layer 1
    dim3 g1(NH / 128, (NN + 127) / 128);
    k_gemm1_tf32<<<g1, 256>>>(x, W1);
    k_agg1<<<NN, 128>>>(b1);

    // layer 2
    dim3 g2(1, (NN + 127) / 128);
    k_gemm2<<<g2, 256>>>(W2);
    k_agg2<<<(NN + 7) / 8, 256>>>(b2, out);
}

// round 4
// speedup vs baseline: 2.0786x; 1.1923x over previous
#include <cuda_runtime.h>
#include <cuda_bf16.h>
#include <cstdint>

// Problem constants
#define NN 50000
#define NE 150000
#define DF 512
#define NH 512
#define NC 47
#define NADJ (NE + NN)

// ---------------- scratch (static __device__ — no allocation) ----------------
__device__ int   g_deg[NN];
__device__ __align__(16) float g_dinv[NN];
__device__ int   g_incl[NN];
__device__ int   g_bsum[128];
__device__ int   g_offs[NN + 1];
__device__ int   g_cursor[NN];
__device__ int   g_adj[NADJ];
__device__ __align__(16) float g_h1[(size_t)NN * NH];   // dinv-scaled x@W1
__device__ __align__(16) float g_a1[(size_t)NN * NH];   // relu(agg1 + b1)
__device__ __align__(16) float g_h2[(size_t)NN * NC];   // dinv-scaled a1@W2

// ---------------- graph prep ----------------
__global__ void k_init_deg() {
    int i = blockIdx.x * blockDim.x + threadIdx.x;
    if (i < NN) g_deg[i] = 1;  // self loop
}

__global__ void k_count_deg(const int* __restrict__ ecol) {
    int e = blockIdx.x * blockDim.x + threadIdx.x;
    if (e < NE) atomicAdd(&g_deg[ecol[e]], 1);
}

__global__ void k_scan_block() {
    __shared__ int s[512];
    int i = blockIdx.x * 512 + threadIdx.x;
    int v = (i < NN) ? g_deg[i] : 0;
    s[threadIdx.x] = v;
    __syncthreads();
    for (int off = 1; off < 512; off <<= 1) {
        int t = (threadIdx.x >= off) ? s[threadIdx.x - off] : 0;
        __syncthreads();
        s[threadIdx.x] += t;
        __syncthreads();
    }
    if (i < NN) g_incl[i] = s[threadIdx.x];
    if (threadIdx.x == 511) g_bsum[blockIdx.x] = s[511];
}

__global__ void k_scan_bsum(int nblocks) {
    if (threadIdx.x == 0 && blockIdx.x == 0) {
        int acc = 0;
        for (int i = 0; i < nblocks; i++) {
            int v = g_bsum[i];
            g_bsum[i] = acc;   // exclusive
            acc += v;
        }
    }
}

__global__ void k_scan_finish() {
    int i = blockIdx.x * blockDim.x + threadIdx.x;
    if (i < NN) {
        int e = g_incl[i] - g_deg[i] + g_bsum[i / 512];
        g_offs[i] = e;
        g_cursor[i] = e;
        g_dinv[i] = rsqrtf((float)g_deg[i]);
    }
    if (i == 0) g_offs[NN] = NADJ;
}

__global__ void k_scatter(const int* __restrict__ erow,
                          const int* __restrict__ ecol) {
    int t = blockIdx.x * blockDim.x + threadIdx.x;
    if (t < NE) {
        int c = ecol[t];
        int p = atomicAdd(&g_cursor[c], 1);
        g_adj[p] = erow[t];
    } else if (t < NADJ) {
        int i = t - NE;
        int p = atomicAdd(&g_cursor[i], 1);
        g_adj[p] = i;
    }
}

// ---------------- helpers ----------------
__device__ __forceinline__ uint32_t f2tf32(float f) {
    uint32_t u;
    asm("cvt.rna.tf32.f32 %0, %1;" : "=r"(u) : "f"(f));
    return u;
}

__device__ __forceinline__ void mma_tf32(float& c0, float& c1, float& c2, float& c3,
                                         uint32_t a0, uint32_t a1, uint32_t a2, uint32_t a3,
                                         uint32_t b0, uint32_t b1) {
    asm volatile(
        "mma.sync.aligned.m16n8k8.row.col.f32.tf32.tf32.f32 "
        "{%0,%1,%2,%3},{%4,%5,%6,%7},{%8,%9},{%0,%1,%2,%3};"
        : "+f"(c0), "+f"(c1), "+f"(c2), "+f"(c3)
        : "r"(a0), "r"(a1), "r"(a2), "r"(a3), "r"(b0), "r"(b1));
}

// ---------------- GEMM1 (TF32 tensor cores) ----------------
// g_h1[m,f] = dinv[m] * sum_k x[m,k] * W1[k,f]
// BM=128, BN=128, BK=32; 128 threads = 4 warps (2M x 2N); warp tile 64x64.
__global__ __launch_bounds__(128) void k_gemm1_tf32(const float* __restrict__ A,
                                                    const float* __restrict__ B) {
    __shared__ __align__(16) uint32_t As[128][36];   // [m][k] pad36: a-frag conflict-free
    __shared__ __align__(16) uint32_t Bs[32][136];   // [k][n] pad136: b-frag conflict-free

    const int tid = threadIdx.x;
    const int lane = tid & 31;
    const int warp = tid >> 5;        // 0..3
    const int wm = warp & 1;
    const int wn = warp >> 1;
    const int gp = lane >> 2;         // 0..7
    const int tq = lane & 3;          // 0..3

    const int rowBase = blockIdx.y * 128;
    const int colBase = blockIdx.x * 128;
    const int warpRow = wm * 64;
    const int warpCol = wn * 64;

    float acc[4][8][4];
#pragma unroll
    for (int mi = 0; mi < 4; mi++)
#pragma unroll
        for (int ni = 0; ni < 8; ni++)
#pragma unroll
            for (int j = 0; j < 4; j++) acc[mi][ni][j] = 0.f;

    for (int k0 = 0; k0 < DF; k0 += 32) {
        // ---- A tile: 128 rows x 32 k = 1024 float4 -> 8 per thread
#pragma unroll
        for (int i = 0; i < 8; i++) {
            int fid = tid + i * 128;
            int r = fid >> 3;        // 0..127
            int q = fid & 7;
            int gr = rowBase + r;
            float4 v = make_float4(0.f, 0.f, 0.f, 0.f);
            if (gr < NN) v = __ldg((const float4*)(A + (size_t)gr * DF + k0 + q * 4));
            uint4 u;
            u.x = f2tf32(v.x); u.y = f2tf32(v.y);
            u.z = f2tf32(v.z); u.w = f2tf32(v.w);
            *(uint4*)(&As[r][q * 4]) = u;
        }
        // ---- B tile: 32 k-rows x 128 cols = 1024 float4 -> 8 per thread
#pragma unroll
        for (int i = 0; i < 8; i++) {
            int fid = tid + i * 128;
            int r = fid >> 5;        // 0..31
            int q = fid & 31;
            float4 v = __ldg((const float4*)(B + (size_t)(k0 + r) * NH + colBase + q * 4));
            uint4 u;
            u.x = f2tf32(v.x); u.y = f2tf32(v.y);
            u.z = f2tf32(v.z); u.w = f2tf32(v.w);
            *(uint4*)(&Bs[r][q * 4]) = u;
        }
        __syncthreads();

#pragma unroll
        for (int kk = 0; kk < 32; kk += 8) {
            uint32_t a[4][4];
#pragma unroll
            for (int mi = 0; mi < 4; mi++) {
                int r0 = warpRow + mi * 16 + gp;
                a[mi][0] = As[r0][kk + tq];
                a[mi][1] = As[r0 + 8][kk + tq];
                a[mi][2] = As[r0][kk + tq + 4];
                a[mi][3] = As[r0 + 8][kk + tq + 4];
            }
            uint32_t b[8][2];
#pragma unroll
            for (int ni = 0; ni < 8; ni++) {
                int c = warpCol + ni * 8 + gp;
                b[ni][0] = Bs[kk + tq][c];
                b[ni][1] = Bs[kk + tq + 4][c];
            }
#pragma unroll
            for (int mi = 0; mi < 4; mi++)
#pragma unroll
                for (int ni = 0; ni < 8; ni++)
                    mma_tf32(acc[mi][ni][0], acc[mi][ni][1],
                             acc[mi][ni][2], acc[mi][ni][3],
                             a[mi][0], a[mi][1], a[mi][2], a[mi][3],
                             b[ni][0], b[ni][1]);
        }
        __syncthreads();
    }

    // ---- epilogue: scale rows by dinv, store
#pragma unroll
    for (int mi = 0; mi < 4; mi++) {
        int r0 = rowBase + warpRow + mi * 16 + gp;
        int r1 = r0 + 8;
        float d0 = (r0 < NN) ? g_dinv[r0] : 0.f;
        float d1 = (r1 < NN) ? g_dinv[r1] : 0.f;
#pragma unroll
        for (int ni = 0; ni < 8; ni++) {
            int c = colBase + warpCol + ni * 8 + tq * 2;
            if (r0 < NN) {
                float2 o = make_float2(d0 * acc[mi][ni][0], d0 * acc[mi][ni][1]);
                *(float2*)(g_h1 + (size_t)r0 * NH + c) = o;
            }
            if (r1 < NN) {
                float2 o = make_float2(d1 * acc[mi][ni][2], d1 * acc[mi][ni][3]);
                *(float2*)(g_h1 + (size_t)r1 * NH + c) = o;
            }
        }
    }
}

// ---------------- agg1: a1[i,f] = relu(dinv[i]*sum_{adj} h1[row,f] + b1[f]) ----------------
__global__ __launch_bounds__(128) void k_agg1(const float* __restrict__ b1) {
    const int node = blockIdx.x;
    const int f = threadIdx.x * 4;  // 128 threads x float4 = 512
    const int s = g_offs[node], e = g_offs[node + 1];
    float4 acc = make_float4(0.f, 0.f, 0.f, 0.f);
    for (int p = s; p < e; p++) {
        int r = g_adj[p];
        float4 v = *(const float4*)(g_h1 + (size_t)r * NH + f);
        acc.x += v.x; acc.y += v.y; acc.z += v.z; acc.w += v.w;
    }
    float d = g_dinv[node];
    float4 bb = *(const float4*)(b1 + f);
    float4 o;
    o.x = fmaxf(d * acc.x + bb.x, 0.f);
    o.y = fmaxf(d * acc.y + bb.y, 0.f);
    o.z = fmaxf(d * acc.z + bb.z, 0.f);
    o.w = fmaxf(d * acc.w + bb.w, 0.f);
    *(float4*)(g_a1 + (size_t)node * NH + f) = o;
}

// ---------------- GEMM2 (TF32): g_h2[m,c] = dinv[m] * sum_k a1[m,k] * W2[k,c] ----------------
// BM=128, BN=64 (guarded to 47), BK=32; 256 threads = 8 warps (4M x 2N); warp tile 32x32.
__global__ __launch_bounds__(256) void k_gemm2_tf32(const float* __restrict__ B) {
    __shared__ __align__(16) uint32_t As[128][36];
    __shared__ __align__(16) uint32_t Bs[32][72];    // pad72: b-frag conflict-free

    const int tid = threadIdx.x;
    const int lane = tid & 31;
    const int warp = tid >> 5;        // 0..7
    const int wm = warp & 3;
    const int wn = warp >> 2;
    const int gp = lane >> 2;
    const int tq = lane & 3;

    const int rowBase = blockIdx.x * 128;
    const int warpRow = wm * 32;
    const int warpCol = wn * 32;

    float acc[2][4][4];
#pragma unroll
    for (int mi = 0; mi < 2; mi++)
#pragma unroll
        for (int ni = 0; ni < 4; ni++)
#pragma unroll
            for (int j = 0; j < 4; j++) acc[mi][ni][j] = 0.f;

    for (int k0 = 0; k0 < NH; k0 += 32) {
        // ---- A tile: 128 x 32 = 1024 float4 -> 4 per thread (from g_a1)
#pragma unroll
        for (int i = 0; i < 4; i++) {
            int fid = tid + i * 256;
            int r = fid >> 3, q = fid & 7;
            int gr = rowBase + r;
            float4 v = make_float4(0.f, 0.f, 0.f, 0.f);
            if (gr < NN) v = __ldg((const float4*)(g_a1 + (size_t)gr * NH + k0 + q * 4));
            uint4 u;
            u.x = f2tf32(v.x); u.y = f2tf32(v.y);
            u.z = f2tf32(v.z); u.w = f2tf32(v.w);
            *(uint4*)(&As[r][q * 4]) = u;
        }
        // ---- B tile: 32 x 64 scalar with col guard (W2 row stride = 47)
#pragma unroll
        for (int i = 0; i < 8; i++) {
            int fid = tid + i * 256;
            int r = fid >> 6, c = fid & 63;
            float v = (c < NC) ? __ldg(B + (size_t)(k0 + r) * NC + c) : 0.f;
            Bs[r][c] = f2tf32(v);
        }
        __syncthreads();

#pragma unroll
        for (int kk = 0; kk < 32; kk += 8) {
            uint32_t a[2][4];
#pragma unroll
            for (int mi = 0; mi < 2; mi++) {
                int r0 = warpRow + mi * 16 + gp;
                a[mi][0] = As[r0][kk + tq];
                a[mi][1] = As[r0 + 8][kk + tq];
                a[mi][2] = As[r0][kk + tq + 4];
                a[mi][3] = As[r0 + 8][kk + tq + 4];
            }
            uint32_t b[4][2];
#pragma unroll
            for (int ni = 0; ni < 4; ni++) {
                int c = warpCol + ni * 8 + gp;
                b[ni][0] = Bs[kk + tq][c];
                b[ni][1] = Bs[kk + tq + 4][c];
            }
#pragma unroll
            for (int mi = 0; mi < 2; mi++)
#pragma unroll
                for (int ni = 0; ni < 4; ni++)
                    mma_tf32(acc[mi][ni][0], acc[mi][ni][1],
                             acc[mi][ni][2], acc[mi][ni][3],
                             a[mi][0], a[mi][1], a[mi][2], a[mi][3],
                             b[ni][0], b[ni][1]);
        }
        __syncthreads();
    }

    // ---- epilogue with N guard
#pragma unroll
    for (int mi = 0; mi < 2; mi++) {
        int r0 = rowBase + warpRow + mi * 16 + gp;
        int r1 = r0 + 8;
        float d0 = (r0 < NN) ? g_dinv[r0] : 0.f;
        float d1 = (r1 < NN) ? g_dinv[r1] : 0.f;
#pragma unroll
        for (int ni = 0; ni < 4; ni++) {
            int c = warpCol + ni * 8 + tq * 2;
            if (r0 < NN) {
                if (c < NC)     g_h2[(size_t)r0 * NC + c]     = d0 * acc[mi][ni][0];
                if (c + 1 < NC) g_h2[(size_t)r0 * NC + c + 1] = d0 * acc[mi][ni][1];
            }
            if (r1 < NN) {
                if (c < NC)     g_h2[(size_t)r1 * NC + c]     = d1 * acc[mi][ni][2];
                if (c + 1 < NC) g_h2[(size_t)r1 * NC + c + 1] = d1 * acc[mi][ni][3];
            }
        }
    }
}

// ---------------- agg2: out[i,c] = dinv[i]*sum_{adj} h2[row,c] + b2[c] ----------------
__global__ __launch_bounds__(256) void k_agg2(const float* __restrict__ b2,
                                              float* __restrict__ out) {
    int node = blockIdx.x * 8 + (threadIdx.x >> 5);
    if (node >= NN) return;
    int lane = threadIdx.x & 31;
    int s = g_offs[node], e = g_offs[node + 1];
    float a0 = 0.f, a1 = 0.f;
    for (int p = s; p < e; p++) {
        int r = g_adj[p];
        const float* gp = g_h2 + (size_t)r * NC;
        a0 += gp[lane];
        if (lane + 32 < NC) a1 += gp[lane + 32];
    }
    float d = g_dinv[node];
    out[(size_t)node * NC + lane] = d * a0 + b2[lane];
    if (lane + 32 < NC)
        out[(size_t)node * NC + lane + 32] = d * a1 + b2[lane + 32];
}

// ---------------- launch ----------------
extern "C" void kernel_launch(void* const* d_in, const int* in_sizes, int n_in,
                              void* d_out, int out_size) {
    const float* x  = (const float*)d_in[0];
    const int*   ei = (const int*)d_in[1];   // [2, NE] int32
    const float* W1 = (const float*)d_in[2];
    const float* b1 = (const float*)d_in[3];
    const float* W2 = (const float*)d_in[4];
    const float* b2 = (const float*)d_in[5];
    float* out = (float*)d_out;

    const int* erow = ei;        // edge_index[0] = source
    const int* ecol = ei + NE;   // edge_index[1] = target

    // graph prep
    k_init_deg<<<(NN + 255) / 256, 256>>>();
    k_count_deg<<<(NE + 255) / 256, 256>>>(ecol);
    int nsb = (NN + 511) / 512;  // 98
    k_scan_block<<<nsb, 512>>>();
    k_scan_bsum<<<1, 32>>>(nsb);
    k_scan_finish<<<(NN + 255) / 256, 256>>>();
    k_scatter<<<(NADJ + 255) / 256, 256>>>(erow, ecol);

    // layer 1
    dim3 g1(NH / 128, (NN + 127) / 128);
    k_gemm1_tf32<<<g1, 128>>>(x, W1);
    k_agg1<<<NN, 128>>>(b1);

    // layer 2
    k_gemm2_tf32<<<(NN + 127) / 128, 256>>>(W2);
    k_agg2<<<(NN + 7) / 8, 256>>>(b2, out);
}